// round 13
// baseline (speedup 1.0000x reference)
#include <cuda_runtime.h>
#include <cstdint>

// GroupGMM as one GEMM on mma.sync bf16 (m16n8k16, fp32 accum):
//   D[8192 x 1040] = A[8192 x 16384] @ Wcat[16384 x 1040]
//   K order = (i_chunk outer, group inner); A[b,·] = g[b,gg] * x[b, ic*32+k]
//   built in registers; bias folded as K-tile 512 (A = g, B = bias).
// R12: BM=128 / 256-thread CTAs, __launch_bounds__(256,2) -> 2 CTAs/SM so
//      barrier drains + LDS/LDG latency of one CTA hide under the other.

#define THREADS 256

namespace {
constexpr int BM = 128, BN = 64, BK = 32;
constexpr int IDIM = 512, GDIM = 32, NTOT = 1040;
constexpr int KTILES = 512;            // GEMM tiles; index 512 = bias tile
constexpr int NPER = 128;              // 4-tile periods

// smem layout (float offsets)
constexpr int XS = 0;                  // x chunk [128][36]
constexpr int GS = 128 * 36;           // g block [128][36]
constexpr int BF = 2 * 128 * 36;       // frag ring (u32): [8 slot][2 wN][2 s][2 h][32 lane][4]
constexpr int SLOT_U32 = 2 * 2 * 2 * 32 * 4;   // 1024 u32 per slot
constexpr int SMEM_FLOATS = BF + 8 * SLOT_U32; // 17408
constexpr int SMEM_BYTES  = SMEM_FLOATS * 4;   // 69632 B per CTA
}  // namespace

__device__ __forceinline__ uint32_t pack_bf16(float lo, float hi) {
    uint32_t r;
    asm("cvt.rn.bf16x2.f32 %0, %1, %2;" : "=r"(r) : "f"(hi), "f"(lo));
    return r;
}
__device__ __forceinline__ void mma_bf16(float* d, const uint32_t* a, const uint32_t* b) {
    asm volatile(
        "mma.sync.aligned.m16n8k16.row.col.f32.bf16.bf16.f32 "
        "{%0,%1,%2,%3}, {%4,%5,%6,%7}, {%8,%9}, {%0,%1,%2,%3};\n"
        : "+f"(d[0]), "+f"(d[1]), "+f"(d[2]), "+f"(d[3])
        : "r"(a[0]), "r"(a[1]), "r"(a[2]), "r"(a[3]), "r"(b[0]), "r"(b[1]));
}
__device__ __forceinline__ float softplus_eps(float z) {
    return fmaxf(z, 0.0f) + log1pf(__expf(-fabsf(z))) + 1e-7f;
}

__global__ __launch_bounds__(THREADS, 2)
void groupgmm_bf16(const float* __restrict__ x,    // [8192,512]
                   const float* __restrict__ gmat, // [8192,32]
                   const float* __restrict__ W_mu, const float* __restrict__ b_mu,
                   const float* __restrict__ W_si, const float* __restrict__ b_si,
                   const float* __restrict__ W_pi, const float* __restrict__ b_pi,
                   float* __restrict__ out)        // [8192,1040]
{
    extern __shared__ float sm[];
    float*    xs = sm + XS;
    float*    gs = sm + GS;
    uint32_t* bf = reinterpret_cast<uint32_t*>(sm + BF);

    const int tid   = threadIdx.x;
    const int lane  = tid & 31;
    const int warp  = tid >> 5;
    const int warpM = warp & 3;    // 4 warps along M (32 rows each)
    const int warpN = warp >> 2;   // 2 warps along N (32 cols each)
    const int m0 = blockIdx.y * BM;
    const int n0 = blockIdx.x * BN;

    // -------- producer role: column nl, k-rows kh*8 .. kh*8+7 (2 sub-roles) --------
    const int nl = tid & 63;
    const int kh = tid >> 6;                 // 0..3
    int nc = n0 + nl; if (nc >= NTOT) nc = NTOT - 1;
    const float *wp, *bp; int On;
    if (nc < 16)       { wp = W_pi + nc;         bp = b_pi + nc;         On = 16;  }
    else if (nc < 528) { wp = W_mu + (nc - 16);  bp = b_mu + (nc - 16);  On = 512; }
    else               { wp = W_si + (nc - 528); bp = b_si + (nc - 528); On = 512; }

    // fragment store coordinates for the 2 sub-roles (khOld = kh*2 + sub)
    const int wNp = nl >> 5;
    const int nsP = (nl >> 3) & 3;
    int stBase[2];
#pragma unroll
    for (int sub = 0; sub < 2; ++sub) {
        const int khO  = kh * 2 + sub;
        const int sP   = khO >> 2;
        const int regP = (khO >> 1) & 1;
        const int uP   = nsP * 2 + regP;
        const int hP   = uP >> 2, posP = uP & 3;
        const int laneP0 = (nl & 7) * 4 + (khO & 1) * 2;
        stBase[sub] = ((wNp * 2 + sP) * 2 + hP) * 128 + laneP0 * 4 + posP;
    }

    // -------- consumer row indices --------
    int rowIx[4];
#pragma unroll
    for (int rid = 0; rid < 4; ++rid)
        rowIx[rid] = warpM * 32 + (rid >> 1) * 16 + (rid & 1) * 8 + (lane >> 2);

    // W base for K-tile t, sub-role sub (t == KTILES -> bias rows)
    auto wbase = [&](int t, int sub) -> const float* {
        const int kr = (kh * 2 + sub) * 4;
        return (t < KTILES)
            ? wp + (size_t)((t & 31) * IDIM + (t >> 5) * BK + kr) * On
            : bp + (size_t)kr * On;
    };

    // -------- prologue: g block + x chunk 0 --------
#pragma unroll
    for (int j = 0; j < 4; ++j) {
        int slot = tid + THREADS * j;        // 1024 float4 slots
        int row = slot >> 3, c4 = (slot & 7) * 4;
        *reinterpret_cast<float4*>(gs + row * 36 + c4) =
            *reinterpret_cast<const float4*>(gmat + (size_t)(m0 + row) * GDIM + c4);
        *reinterpret_cast<float4*>(xs + row * 36 + c4) =
            *reinterpret_cast<const float4*>(x + (size_t)(m0 + row) * IDIM + c4);
    }

    // -------- produce tiles 0..3 into slots 0..3 --------
#pragma unroll
    for (int j = 0; j < 4; ++j) {
        uint32_t* sl = bf + j * SLOT_U32;
#pragma unroll
        for (int sub = 0; sub < 2; ++sub) {
            const float* base = wbase(j, sub);
            float w0 = base[0], w1 = base[(size_t)On], w2 = base[(size_t)2 * On],
                  w3 = base[(size_t)3 * On];
            sl[stBase[sub]]     = pack_bf16(w0, w1);
            sl[stBase[sub] + 4] = pack_bf16(w2, w3);
        }
    }
    __syncthreads();

    float acc[2][4][4];
#pragma unroll
    for (int a = 0; a < 2; ++a)
#pragma unroll
        for (int b = 0; b < 4; ++b)
#pragma unroll
            for (int c = 0; c < 4; ++c) acc[a][b][c] = 0.0f;

    float xr[4][8];   // x fragments: [rowId][k = 8j + 2(lane&3) + h]

    // consume one GEMM K-tile (t < KTILES)
    auto consume = [&](int t) {
        const int gg = t & 31;
        float gv[4];
#pragma unroll
        for (int rid = 0; rid < 4; ++rid) gv[rid] = gs[rowIx[rid] * 36 + gg];

        const uint32_t* sl = bf + (t & 7) * SLOT_U32 + warpN * 512;
#pragma unroll
        for (int s = 0; s < 2; ++s) {
            uint4 v0 = *reinterpret_cast<const uint4*>(sl + s * 256 + lane * 4);
            uint4 v1 = *reinterpret_cast<const uint4*>(sl + s * 256 + 128 + lane * 4);
            uint32_t bU[8] = {v0.x, v0.y, v0.z, v0.w, v1.x, v1.y, v1.z, v1.w};
            uint32_t aUs[8];
#pragma unroll
            for (int ms = 0; ms < 2; ++ms) {
                const int r0 = ms * 2, r1 = ms * 2 + 1;
                aUs[ms*4+0] = pack_bf16(xr[r0][4*s  ] * gv[r0], xr[r0][4*s+1] * gv[r0]);
                aUs[ms*4+1] = pack_bf16(xr[r1][4*s  ] * gv[r1], xr[r1][4*s+1] * gv[r1]);
                aUs[ms*4+2] = pack_bf16(xr[r0][4*s+2] * gv[r0], xr[r0][4*s+3] * gv[r0]);
                aUs[ms*4+3] = pack_bf16(xr[r1][4*s+2] * gv[r1], xr[r1][4*s+3] * gv[r1]);
            }
#pragma unroll
            for (int ms = 0; ms < 2; ++ms)
#pragma unroll
                for (int ns = 0; ns < 4; ++ns)
                    mma_bf16(acc[ms][ns], &aUs[ms * 4], &bU[ns * 2]);
        }
    };

    float wv[16];   // W prefetch buffer: 2 tiles x 2 subs x 4 rows

    // -------- main loop: 128 periods of 4 tiles --------
    for (int p = 0; p < NPER; ++p) {
        const int T = p * 4;

        // prefetch W for tiles T+4, T+5
#pragma unroll
        for (int jj = 0; jj < 2; ++jj) {
            const int t = T + 4 + jj;
            if (t <= KTILES) {
#pragma unroll
                for (int sub = 0; sub < 2; ++sub) {
                    const float* base = wbase(t, sub);
#pragma unroll
                    for (int r = 0; r < 4; ++r)
                        wv[(jj * 2 + sub) * 4 + r] = base[(size_t)r * On];
                }
            }
        }

        // refresh x fragments at i_chunk boundary (every 8 periods)
        if ((T & 31) == 0) {
#pragma unroll
            for (int rid = 0; rid < 4; ++rid) {
                const float* rp = xs + rowIx[rid] * 36 + (lane & 3) * 2;
#pragma unroll
                for (int j = 0; j < 4; ++j) {
                    float2 v = *reinterpret_cast<const float2*>(rp + 8 * j);
                    xr[rid][2 * j] = v.x; xr[rid][2 * j + 1] = v.y;
                }
            }
        }

        consume(T + 0);
        consume(T + 1);

        // store W frags for T+4, T+5
#pragma unroll
        for (int jj = 0; jj < 2; ++jj) {
            const int t = T + 4 + jj;
            if (t <= KTILES) {
                uint32_t* sl = bf + (t & 7) * SLOT_U32;
#pragma unroll
                for (int sub = 0; sub < 2; ++sub) {
                    sl[stBase[sub]]     = pack_bf16(wv[(jj*2+sub)*4 + 0], wv[(jj*2+sub)*4 + 1]);
                    sl[stBase[sub] + 4] = pack_bf16(wv[(jj*2+sub)*4 + 2], wv[(jj*2+sub)*4 + 3]);
                }
            }
        }

        // prefetch W for tiles T+6, T+7
#pragma unroll
        for (int jj = 0; jj < 2; ++jj) {
            const int t = T + 6 + jj;
            if (t <= KTILES) {
#pragma unroll
                for (int sub = 0; sub < 2; ++sub) {
                    const float* base = wbase(t, sub);
#pragma unroll
                    for (int r = 0; r < 4; ++r)
                        wv[(jj * 2 + sub) * 4 + r] = base[(size_t)r * On];
                }
            }
        }

        consume(T + 2);
        consume(T + 3);

        // refill xs with next i_chunk one period after the boundary
        if ((T & 31) == 4 && T < 480) {
            const int icn = (T >> 5) + 1;
#pragma unroll
            for (int j = 0; j < 4; ++j) {
                int slot = tid + THREADS * j;
                int row = slot >> 3, c4 = (slot & 7) * 4;
                *reinterpret_cast<float4*>(xs + row * 36 + c4) =
                    *reinterpret_cast<const float4*>(
                        x + (size_t)(m0 + row) * IDIM + icn * BK + c4);
            }
        }

        // store W frags for T+6, T+7
#pragma unroll
        for (int jj = 0; jj < 2; ++jj) {
            const int t = T + 6 + jj;
            if (t <= KTILES) {
                uint32_t* sl = bf + (t & 7) * SLOT_U32;
#pragma unroll
                for (int sub = 0; sub < 2; ++sub) {
                    sl[stBase[sub]]     = pack_bf16(wv[(jj*2+sub)*4 + 0], wv[(jj*2+sub)*4 + 1]);
                    sl[stBase[sub] + 4] = pack_bf16(wv[(jj*2+sub)*4 + 2], wv[(jj*2+sub)*4 + 3]);
                }
            }
        }

        __syncthreads();
    }

    // -------- bias tile (t = 512): A = g block, slot 0 --------
    {
#pragma unroll
        for (int rid = 0; rid < 4; ++rid) {
            const float* rp = gs + rowIx[rid] * 36 + (lane & 3) * 2;
#pragma unroll
            for (int j = 0; j < 4; ++j) {
                float2 v = *reinterpret_cast<const float2*>(rp + 8 * j);
                xr[rid][2 * j] = v.x; xr[rid][2 * j + 1] = v.y;
            }
        }
        const uint32_t* sl = bf + 0 * SLOT_U32 + warpN * 512;
#pragma unroll
        for (int s = 0; s < 2; ++s) {
            uint4 v0 = *reinterpret_cast<const uint4*>(sl + s * 256 + lane * 4);
            uint4 v1 = *reinterpret_cast<const uint4*>(sl + s * 256 + 128 + lane * 4);
            uint32_t bU[8] = {v0.x, v0.y, v0.z, v0.w, v1.x, v1.y, v1.z, v1.w};
            uint32_t aUs[8];
#pragma unroll
            for (int ms = 0; ms < 2; ++ms) {
                const int r0 = ms * 2, r1 = ms * 2 + 1;
                aUs[ms*4+0] = pack_bf16(xr[r0][4*s  ], xr[r0][4*s+1]);
                aUs[ms*4+1] = pack_bf16(xr[r1][4*s  ], xr[r1][4*s+1]);
                aUs[ms*4+2] = pack_bf16(xr[r0][4*s+2], xr[r0][4*s+3]);
                aUs[ms*4+3] = pack_bf16(xr[r1][4*s+2], xr[r1][4*s+3]);
            }
#pragma unroll
            for (int ms = 0; ms < 2; ++ms)
#pragma unroll
                for (int ns = 0; ns < 4; ++ns)
                    mma_bf16(acc[ms][ns], &aUs[ms * 4], &bU[ns * 2]);
        }
    }

    // -------- epilogue: activation + store --------
#pragma unroll
    for (int ms = 0; ms < 2; ++ms) {
#pragma unroll
        for (int ns = 0; ns < 4; ++ns) {
            const int rA = m0 + warpM * 32 + ms * 16 + (lane >> 2);
            const int c0 = n0 + warpN * 32 + ns * 8 + (lane & 3) * 2;
            if (c0 < NTOT) {
                const bool sig = (c0 >= 528);
                float v0 = acc[ms][ns][0], v1 = acc[ms][ns][1];
                float v2 = acc[ms][ns][2], v3 = acc[ms][ns][3];
                if (sig) {
                    v0 = softplus_eps(v0); v1 = softplus_eps(v1);
                    v2 = softplus_eps(v2); v3 = softplus_eps(v3);
                }
                *reinterpret_cast<float2*>(out + (size_t)rA * NTOT + c0)       = make_float2(v0, v1);
                *reinterpret_cast<float2*>(out + (size_t)(rA + 8) * NTOT + c0) = make_float2(v2, v3);
            }
        }
    }
}

extern "C" void kernel_launch(void* const* d_in, const int* in_sizes, int n_in,
                              void* d_out, int out_size) {
    const float* x    = (const float*)d_in[0];
    const float* g    = (const float*)d_in[1];
    const float* W_mu = (const float*)d_in[2];
    const float* b_mu = (const float*)d_in[3];
    const float* W_si = (const float*)d_in[4];
    const float* b_si = (const float*)d_in[5];
    const float* W_pi = (const float*)d_in[6];
    const float* b_pi = (const float*)d_in[7];
    float* out = (float*)d_out;

    cudaFuncSetAttribute(groupgmm_bf16,
                         cudaFuncAttributeMaxDynamicSharedMemorySize, SMEM_BYTES);

    dim3 grid((NTOT + BN - 1) / BN, 8192 / BM);  // (17, 64) = 1088 CTAs
    groupgmm_bf16<<<grid, THREADS, SMEM_BYTES>>>(x, g, W_mu, b_mu, W_si, b_si,
                                                 W_pi, b_pi, out);
}

// round 14
// speedup vs baseline: 1.3244x; 1.3244x over previous
#include <cuda_runtime.h>
#include <cstdint>

// GroupGMM as one GEMM on mma.sync bf16 (m16n8k16, fp32 accum):
//   D[8192 x 1040] = A[8192 x 16384] @ Wcat[16384 x 1040]
//   K order = (i_chunk outer, group inner); A[b,·] = g[b,gg] * x[b, ic*32+k]
//   built in registers; bias folded as K-tile 512 (A = g, B = bias).
// R13: BM=256 / BN=32 / 256 threads, __launch_bounds__(256,2): 2 CTAs/SM for
//      latency hiding WITHOUT duplicating W traffic (N-split, not M-split).

#define THREADS 256

namespace {
constexpr int BM = 256, BN = 32, BK = 32;
constexpr int IDIM = 512, GDIM = 32, NTOT = 1040;
constexpr int KTILES = 512;            // GEMM tiles; index 512 = bias tile
constexpr int NPER = 128;              // 4-tile periods

// smem layout (float offsets)
constexpr int XS = 0;                  // x chunk [256][36]
constexpr int GS = 256 * 36;           // g block [256][36]
constexpr int BF = 2 * 256 * 36;       // frag ring (u32): [8 slot][2 s][2 h][32 lane][4]
constexpr int SLOT_U32 = 2 * 2 * 32 * 4;       // 512 u32 per slot
constexpr int SMEM_FLOATS = BF + 8 * SLOT_U32; // 22528
constexpr int SMEM_BYTES  = SMEM_FLOATS * 4;   // 90112 B per CTA
}  // namespace

__device__ __forceinline__ uint32_t pack_bf16(float lo, float hi) {
    uint32_t r;
    asm("cvt.rn.bf16x2.f32 %0, %1, %2;" : "=r"(r) : "f"(hi), "f"(lo));
    return r;
}
__device__ __forceinline__ void mma_bf16(float* d, const uint32_t* a, const uint32_t* b) {
    asm volatile(
        "mma.sync.aligned.m16n8k16.row.col.f32.bf16.bf16.f32 "
        "{%0,%1,%2,%3}, {%4,%5,%6,%7}, {%8,%9}, {%0,%1,%2,%3};\n"
        : "+f"(d[0]), "+f"(d[1]), "+f"(d[2]), "+f"(d[3])
        : "r"(a[0]), "r"(a[1]), "r"(a[2]), "r"(a[3]), "r"(b[0]), "r"(b[1]));
}
__device__ __forceinline__ float softplus_eps(float z) {
    return fmaxf(z, 0.0f) + log1pf(__expf(-fabsf(z))) + 1e-7f;
}

__global__ __launch_bounds__(THREADS, 2)
void groupgmm_bf16(const float* __restrict__ x,    // [8192,512]
                   const float* __restrict__ gmat, // [8192,32]
                   const float* __restrict__ W_mu, const float* __restrict__ b_mu,
                   const float* __restrict__ W_si, const float* __restrict__ b_si,
                   const float* __restrict__ W_pi, const float* __restrict__ b_pi,
                   float* __restrict__ out)        // [8192,1040]
{
    extern __shared__ float sm[];
    float*    xs = sm + XS;
    float*    gs = sm + GS;
    uint32_t* bf = reinterpret_cast<uint32_t*>(sm + BF);

    const int tid   = threadIdx.x;
    const int lane  = tid & 31;
    const int warp  = tid >> 5;       // 8 warps, each 32 M-rows x all 32 N-cols
    const int m0 = blockIdx.y * BM;
    const int n0 = blockIdx.x * BN;

    // -------- producer role: column nl (0..31), k-rows kh*4 .. kh*4+3 --------
    const int nl = tid & 31;
    const int kh = tid >> 5;                 // 0..7
    int nc = n0 + nl; if (nc >= NTOT) nc = NTOT - 1;
    const float *wp, *bp; int On;
    if (nc < 16)       { wp = W_pi + nc;         bp = b_pi + nc;         On = 16;  }
    else if (nc < 528) { wp = W_mu + (nc - 16);  bp = b_mu + (nc - 16);  On = 512; }
    else               { wp = W_si + (nc - 528); bp = b_si + (nc - 528); On = 512; }
    // fragment store coordinates (conflict-free layout, slot = [2 s][2 h][32 lane][4])
    const int sP   = kh >> 2;                // k16 step
    const int regP = (kh >> 1) & 1;          // frag reg (k low/high 8)
    const int nsP  = (nl >> 3) & 3;
    const int uP   = nsP * 2 + regP;
    const int hP   = uP >> 2, posP = uP & 3;
    const int laneP0 = (nl & 7) * 4 + (kh & 1) * 2;
    const int stBase = (sP * 2 + hP) * 128 + laneP0 * 4 + posP;

    // -------- consumer row indices --------
    int rowIx[4];
#pragma unroll
    for (int rid = 0; rid < 4; ++rid)
        rowIx[rid] = warp * 32 + (rid >> 1) * 16 + (rid & 1) * 8 + (lane >> 2);

    // W base for K-tile t (t == KTILES -> bias rows)
    auto wbase = [&](int t) -> const float* {
        return (t < KTILES)
            ? wp + (size_t)((t & 31) * IDIM + (t >> 5) * BK + kh * 4) * On
            : bp + (size_t)(kh * 4) * On;
    };

    // -------- prologue: g block + x chunk 0 --------
#pragma unroll
    for (int j = 0; j < 8; ++j) {
        int slot = tid + THREADS * j;        // 2048 float4 slots
        int row = slot >> 3, c4 = (slot & 7) * 4;
        *reinterpret_cast<float4*>(gs + row * 36 + c4) =
            *reinterpret_cast<const float4*>(gmat + (size_t)(m0 + row) * GDIM + c4);
        *reinterpret_cast<float4*>(xs + row * 36 + c4) =
            *reinterpret_cast<const float4*>(x + (size_t)(m0 + row) * IDIM + c4);
    }

    // -------- produce tiles 0..3 into slots 0..3 --------
    float wv[16];
#pragma unroll
    for (int j = 0; j < 4; ++j) {
        const float* base = wbase(j);
#pragma unroll
        for (int r = 0; r < 4; ++r) wv[j * 4 + r] = base[(size_t)r * On];
    }
#pragma unroll
    for (int j = 0; j < 4; ++j) {
        uint32_t* sl = bf + j * SLOT_U32;
        sl[stBase]     = pack_bf16(wv[j * 4 + 0], wv[j * 4 + 1]);
        sl[stBase + 4] = pack_bf16(wv[j * 4 + 2], wv[j * 4 + 3]);
    }
    __syncthreads();

    float acc[2][4][4];
#pragma unroll
    for (int a = 0; a < 2; ++a)
#pragma unroll
        for (int b = 0; b < 4; ++b)
#pragma unroll
            for (int c = 0; c < 4; ++c) acc[a][b][c] = 0.0f;

    float xr[4][8];   // x fragments: [rowId][k = 8j + 2(lane&3) + h]

    // -------- main loop: 128 periods of 4 tiles --------
    for (int p = 0; p < NPER; ++p) {
        const int T = p * 4;

        // W prefetch for period p+1 (tiles T+4..T+7; 512 = bias, >512 skipped)
#pragma unroll
        for (int j = 0; j < 4; ++j) {
            const int t = T + 4 + j;
            if (t <= KTILES) {
                const float* base = wbase(t);
#pragma unroll
                for (int r = 0; r < 4; ++r) wv[j * 4 + r] = base[(size_t)r * On];
            }
        }

        // refresh x fragments at i_chunk boundary (every 8 periods)
        if ((T & 31) == 0) {
#pragma unroll
            for (int rid = 0; rid < 4; ++rid) {
                const float* rp = xs + rowIx[rid] * 36 + (lane & 3) * 2;
#pragma unroll
                for (int j = 0; j < 4; ++j) {
                    float2 v = *reinterpret_cast<const float2*>(rp + 8 * j);
                    xr[rid][2 * j] = v.x; xr[rid][2 * j + 1] = v.y;
                }
            }
        }

        // consume 4 tiles
#pragma unroll
        for (int u = 0; u < 4; ++u) {
            const int t = T + u;
            const int gg = t & 31;
            float gv[4];
#pragma unroll
            for (int rid = 0; rid < 4; ++rid) gv[rid] = gs[rowIx[rid] * 36 + gg];

            const uint32_t* sl = bf + (t & 7) * SLOT_U32;
#pragma unroll
            for (int s = 0; s < 2; ++s) {
                // B frags: 2 conflict-free LDS.128
                uint4 v0 = *reinterpret_cast<const uint4*>(sl + s * 256 + lane * 4);
                uint4 v1 = *reinterpret_cast<const uint4*>(sl + s * 256 + 128 + lane * 4);
                uint32_t bU[8] = {v0.x, v0.y, v0.z, v0.w, v1.x, v1.y, v1.z, v1.w};
                // A frags just-in-time
                uint32_t aUs[8];
#pragma unroll
                for (int ms = 0; ms < 2; ++ms) {
                    const int r0 = ms * 2, r1 = ms * 2 + 1;
                    aUs[ms*4+0] = pack_bf16(xr[r0][4*s  ] * gv[r0], xr[r0][4*s+1] * gv[r0]);
                    aUs[ms*4+1] = pack_bf16(xr[r1][4*s  ] * gv[r1], xr[r1][4*s+1] * gv[r1]);
                    aUs[ms*4+2] = pack_bf16(xr[r0][4*s+2] * gv[r0], xr[r0][4*s+3] * gv[r0]);
                    aUs[ms*4+3] = pack_bf16(xr[r1][4*s+2] * gv[r1], xr[r1][4*s+3] * gv[r1]);
                }
#pragma unroll
                for (int ms = 0; ms < 2; ++ms)
#pragma unroll
                    for (int ns = 0; ns < 4; ++ns)
                        mma_bf16(acc[ms][ns], &aUs[ms * 4], &bU[ns * 2]);
            }
        }

        // refill xs with next i_chunk one period after the boundary
        if ((T & 31) == 4 && T < 480) {
            const int icn = (T >> 5) + 1;
#pragma unroll
            for (int j = 0; j < 8; ++j) {
                int slot = tid + THREADS * j;
                int row = slot >> 3, c4 = (slot & 7) * 4;
                *reinterpret_cast<float4*>(xs + row * 36 + c4) =
                    *reinterpret_cast<const float4*>(
                        x + (size_t)(m0 + row) * IDIM + icn * BK + c4);
            }
        }

        // produce period p+1 fragments into the other ring bank
#pragma unroll
        for (int j = 0; j < 4; ++j) {
            const int t = T + 4 + j;
            if (t <= KTILES) {
                uint32_t* sl = bf + (t & 7) * SLOT_U32;
                sl[stBase]     = pack_bf16(wv[j * 4 + 0], wv[j * 4 + 1]);
                sl[stBase + 4] = pack_bf16(wv[j * 4 + 2], wv[j * 4 + 3]);
            }
        }

        __syncthreads();
    }

    // -------- bias tile (t = 512): A = g block, slot 0 --------
    {
#pragma unroll
        for (int rid = 0; rid < 4; ++rid) {
            const float* rp = gs + rowIx[rid] * 36 + (lane & 3) * 2;
#pragma unroll
            for (int j = 0; j < 4; ++j) {
                float2 v = *reinterpret_cast<const float2*>(rp + 8 * j);
                xr[rid][2 * j] = v.x; xr[rid][2 * j + 1] = v.y;
            }
        }
        const uint32_t* sl = bf + 0 * SLOT_U32;
#pragma unroll
        for (int s = 0; s < 2; ++s) {
            uint4 v0 = *reinterpret_cast<const uint4*>(sl + s * 256 + lane * 4);
            uint4 v1 = *reinterpret_cast<const uint4*>(sl + s * 256 + 128 + lane * 4);
            uint32_t bU[8] = {v0.x, v0.y, v0.z, v0.w, v1.x, v1.y, v1.z, v1.w};
            uint32_t aUs[8];
#pragma unroll
            for (int ms = 0; ms < 2; ++ms) {
                const int r0 = ms * 2, r1 = ms * 2 + 1;
                aUs[ms*4+0] = pack_bf16(xr[r0][4*s  ], xr[r0][4*s+1]);
                aUs[ms*4+1] = pack_bf16(xr[r1][4*s  ], xr[r1][4*s+1]);
                aUs[ms*4+2] = pack_bf16(xr[r0][4*s+2], xr[r0][4*s+3]);
                aUs[ms*4+3] = pack_bf16(xr[r1][4*s+2], xr[r1][4*s+3]);
            }
#pragma unroll
            for (int ms = 0; ms < 2; ++ms)
#pragma unroll
                for (int ns = 0; ns < 4; ++ns)
                    mma_bf16(acc[ms][ns], &aUs[ms * 4], &bU[ns * 2]);
        }
    }

    // -------- epilogue: activation + store --------
#pragma unroll
    for (int ms = 0; ms < 2; ++ms) {
#pragma unroll
        for (int ns = 0; ns < 4; ++ns) {
            const int rA = m0 + warp * 32 + ms * 16 + (lane >> 2);
            const int c0 = n0 + ns * 8 + (lane & 3) * 2;
            if (c0 < NTOT) {
                const bool sig = (c0 >= 528);
                float v0 = acc[ms][ns][0], v1 = acc[ms][ns][1];
                float v2 = acc[ms][ns][2], v3 = acc[ms][ns][3];
                if (sig) {
                    v0 = softplus_eps(v0); v1 = softplus_eps(v1);
                    v2 = softplus_eps(v2); v3 = softplus_eps(v3);
                }
                *reinterpret_cast<float2*>(out + (size_t)rA * NTOT + c0)       = make_float2(v0, v1);
                *reinterpret_cast<float2*>(out + (size_t)(rA + 8) * NTOT + c0) = make_float2(v2, v3);
            }
        }
    }
}

extern "C" void kernel_launch(void* const* d_in, const int* in_sizes, int n_in,
                              void* d_out, int out_size) {
    const float* x    = (const float*)d_in[0];
    const float* g    = (const float*)d_in[1];
    const float* W_mu = (const float*)d_in[2];
    const float* b_mu = (const float*)d_in[3];
    const float* W_si = (const float*)d_in[4];
    const float* b_si = (const float*)d_in[5];
    const float* W_pi = (const float*)d_in[6];
    const float* b_pi = (const float*)d_in[7];
    float* out = (float*)d_out;

    cudaFuncSetAttribute(groupgmm_bf16,
                         cudaFuncAttributeMaxDynamicSharedMemorySize, SMEM_BYTES);

    dim3 grid((NTOT + BN - 1) / BN, 8192 / BM);  // (33, 32) = 1056 CTAs
    groupgmm_bf16<<<grid, THREADS, SMEM_BYTES>>>(x, g, W_mu, b_mu, W_si, b_si,
                                                 W_pi, b_pi, out);
}